// round 2
// baseline (speedup 1.0000x reference)
#include <cuda_runtime.h>

#define B_   32
#define C_   4
#define N_   16384
#define RES_ 32
#define NVOX (B_ * RES_ * RES_ * RES_)    // 1048576
#define NB   512                          // refl blocks: 16 per batch
#define PTS_PER_BLK 1024                  // 256 threads * 4 points

// Scratch (allocation-free): padded float4 copy of voxel_grid_cp -> LDG.128 gathers.
__device__ float4 g_cp_pad[NVOX];         // 16 MB
__device__ float  g_partials[NB];
__device__ int    g_count = 0;            // reset to 0 by last block each run

// ---------------------------------------------------------------------------
// Pad voxel_grid_cp [B,32,32,32,3] -> float4. Vectorized: 4 voxels per thread
// (3x LDG.128 in, 4x STG.128 out). Pure-BW kernel, ~28.6 MB traffic.
// ---------------------------------------------------------------------------
__global__ void __launch_bounds__(256) pad_kernel(const float4* __restrict__ cp4) {
    int i = blockIdx.x * 256 + threadIdx.x;      // 0 .. NVOX/4-1
    float4 a = cp4[3 * i + 0];
    float4 b = cp4[3 * i + 1];
    float4 c = cp4[3 * i + 2];
    g_cp_pad[4 * i + 0] = make_float4(a.x, a.y, a.z, 0.0f);
    g_cp_pad[4 * i + 1] = make_float4(a.w, b.x, b.y, 0.0f);
    g_cp_pad[4 * i + 2] = make_float4(b.z, b.w, c.x, 0.0f);
    g_cp_pad[4 * i + 3] = make_float4(c.y, c.z, c.w, 0.0f);
}

// ---------------------------------------------------------------------------
// Main: reflect 4 points/thread through 4 planes, gather cp, sum norms.
// Last block (threadfence + counter) folds in the regularizer and the final
// deterministic reduction, then resets the counter for graph replay.
// ---------------------------------------------------------------------------
__global__ void __launch_bounds__(256) refl_kernel(const float* __restrict__ y_pred,
                                                   const float* __restrict__ points,
                                                   float* __restrict__ out) {
    const int b  = blockIdx.x >> 4;               // 16 blocks per batch
    const int n0 = ((blockIdx.x & 15) << 10) + threadIdx.x;

    __shared__ float4 plane[4];                   // n_hat.xyz, d
    if (threadIdx.x < 4) {
        const float* yp = y_pred + (b * 4 + threadIdx.x) * 4;
        float nx = yp[0], ny = yp[1], nz = yp[2];
        float inv = rsqrtf(nx*nx + ny*ny + nz*nz);
        plane[threadIdx.x] = make_float4(nx*inv, ny*inv, nz*inv, yp[3]);
    }
    __syncthreads();

    const float4* cpb = g_cp_pad + (b << 15);     // b * 32768
    const float*  pb  = points + (size_t)b * N_ * 3;

    float acc = 0.0f;
#pragma unroll
    for (int k = 0; k < 4; k++) {
        const int n = n0 + (k << 8);
        const float* pp = pb + n * 3;
        float px = pp[0], py = pp[1], pz = pp[2];
#pragma unroll
        for (int c = 0; c < 4; c++) {
            float4 pl = plane[c];
            float t  = 2.0f * (px*pl.x + py*pl.y + pz*pl.z + pl.w);
            float rx = fmaf(-t, pl.x, px);
            float ry = fmaf(-t, pl.y, py);
            float rz = fmaf(-t, pl.z, pz);
            int v0 = min(RES_ - 1, max(0, __float2int_rd(rx * (float)RES_)));
            int v1 = min(RES_ - 1, max(0, __float2int_rd(ry * (float)RES_)));
            int v2 = min(RES_ - 1, max(0, __float2int_rd(rz * (float)RES_)));
            float4 cpv = __ldg(&cpb[(v0 << 10) | (v1 << 5) | v2]);
            float dx = rx - cpv.x, dy = ry - cpv.y, dz = rz - cpv.z;
            acc += sqrtf(fmaf(dx, dx, fmaf(dy, dy, dz * dz)));
        }
    }

    // Deterministic block reduction (fixed order), no float atomics.
#pragma unroll
    for (int off = 16; off >= 1; off >>= 1)
        acc += __shfl_xor_sync(0xffffffffu, acc, off);
    __shared__ float ws[8];
    const int wid = threadIdx.x >> 5;
    if ((threadIdx.x & 31) == 0) ws[wid] = acc;
    __syncthreads();
    if (threadIdx.x == 0) {
        float s = 0.0f;
#pragma unroll
        for (int w = 0; w < 8; w++) s += ws[w];
        g_partials[blockIdx.x] = s;
    }

    // ---- last-block final reduction ----
    __shared__ bool is_last;
    __threadfence();
    if (threadIdx.x == 0) {
        int done = atomicAdd(&g_count, 1);
        is_last = (done == NB - 1);
    }
    __syncthreads();
    if (!is_last) return;

    // Regularizer: 25 * mean_b ||n_hat n_hat^T - I||_F  (warp 0, one lane/batch)
    __shared__ float reg_s;
    if (threadIdx.x < 32) {
        const float* yp = y_pred + threadIdx.x * 16;
        float nh[4][3];
#pragma unroll
        for (int c = 0; c < 4; c++) {
            float nx = yp[c*4+0], ny = yp[c*4+1], nz = yp[c*4+2];
            float inv = rsqrtf(nx*nx + ny*ny + nz*nz);
            nh[c][0] = nx*inv; nh[c][1] = ny*inv; nh[c][2] = nz*inv;
        }
        float s = 0.0f;
#pragma unroll
        for (int c = 0; c < 4; c++)
#pragma unroll
            for (int e = 0; e < 4; e++) {
                float g = nh[c][0]*nh[e][0] + nh[c][1]*nh[e][1] + nh[c][2]*nh[e][2]
                          - (c == e ? 1.0f : 0.0f);
                s += g * g;
            }
        float reg = sqrtf(s);
#pragma unroll
        for (int off = 16; off >= 1; off >>= 1)
            reg += __shfl_xor_sync(0xffffffffu, reg, off);
        if (threadIdx.x == 0) reg_s = 25.0f * reg * (1.0f / (float)B_);
    }

    // Sum all partials in fixed order.
    __shared__ float red[256];
    float a = 0.0f;
#pragma unroll
    for (int i = threadIdx.x; i < NB; i += 256) a += g_partials[i];
    red[threadIdx.x] = a;
    __syncthreads();
#pragma unroll
    for (int stride = 128; stride >= 1; stride >>= 1) {
        if (threadIdx.x < stride) red[threadIdx.x] += red[threadIdx.x + stride];
        __syncthreads();
    }
    if (threadIdx.x == 0) {
        out[0]  = red[0] * (1.0f / (float)N_) + reg_s;
        g_count = 0;                               // reset for next graph replay
    }
}

extern "C" void kernel_launch(void* const* d_in, const int* in_sizes, int n_in,
                              void* d_out, int out_size) {
    const float* y_pred = (const float*)d_in[0];
    const float* points = (const float*)d_in[1];
    // d_in[2] = voxel_grid — unused by the reference math.
    const float4* cp4   = (const float4*)d_in[3];
    float* out = (float*)d_out;

    pad_kernel<<<NVOX / 4 / 256, 256>>>(cp4);
    refl_kernel<<<NB, 256>>>(y_pred, points, out);
}

// round 4
// speedup vs baseline: 1.0069x; 1.0069x over previous
#include <cuda_runtime.h>

#define B_   32
#define C_   4
#define N_   16384
#define RES_ 32
#define NVOX (B_ * RES_ * RES_ * RES_)    // 1048576
#define NB   2048                         // refl blocks: 64 per batch, 256 pts each

// Scratch (allocation-free): padded float4 copy of voxel_grid_cp -> LDG.128 gathers.
__device__ float4 g_cp_pad[NVOX];         // 16 MB
__device__ float  g_partials[NB];
__device__ int    g_count = 0;            // reset to 0 by last block each run

// ---------------------------------------------------------------------------
// Pad voxel_grid_cp [B,32,32,32,3] -> float4 (4 voxels / thread, all LDG/STG.128).
// ---------------------------------------------------------------------------
__global__ void __launch_bounds__(256) pad_kernel(const float4* __restrict__ cp4) {
    int i = blockIdx.x * 256 + threadIdx.x;      // 0 .. NVOX/4-1
    float4 a = cp4[3 * i + 0];
    float4 b = cp4[3 * i + 1];
    float4 c = cp4[3 * i + 2];
    g_cp_pad[4 * i + 0] = make_float4(a.x, a.y, a.z, 0.0f);
    g_cp_pad[4 * i + 1] = make_float4(a.w, b.x, b.y, 0.0f);
    g_cp_pad[4 * i + 2] = make_float4(b.z, b.w, c.x, 0.0f);
    g_cp_pad[4 * i + 3] = make_float4(c.y, c.z, c.w, 0.0f);
}

// ---------------------------------------------------------------------------
// Main: 1 point/thread, 4 planes; gather cp via LDG.128; fused final reduce.
// ---------------------------------------------------------------------------
__global__ void __launch_bounds__(256) refl_kernel(const float* __restrict__ y_pred,
                                                   const float* __restrict__ points,
                                                   float* __restrict__ out) {
    const int b  = blockIdx.x >> 6;               // 64 blocks per batch
    const int n0 = (blockIdx.x & 63) << 8;        // first point of this block

    __shared__ float4 plane[4];                   // n_hat.xyz, d
    __shared__ float  spts[768];                  // 256 points * xyz
    if (threadIdx.x < 4) {
        const float* yp = y_pred + (b * 4 + threadIdx.x) * 4;
        float nx = yp[0], ny = yp[1], nz = yp[2];
        float inv = rsqrtf(nx*nx + ny*ny + nz*nz);
        plane[threadIdx.x] = make_float4(nx*inv, ny*inv, nz*inv, yp[3]);
    }
    // Stage this block's 256 points (768 floats = 192 float4, 16B-aligned).
    if (threadIdx.x < 192) {
        const float4* src = (const float4*)(points + ((size_t)b * N_ + n0) * 3);
        ((float4*)spts)[threadIdx.x] = src[threadIdx.x];
    }
    __syncthreads();

    const float px = spts[3 * threadIdx.x + 0];
    const float py = spts[3 * threadIdx.x + 1];
    const float pz = spts[3 * threadIdx.x + 2];

    const float4* cpb = g_cp_pad + (b << 15);     // b * 32768
    float acc = 0.0f;
#pragma unroll
    for (int c = 0; c < 4; c++) {
        float4 pl = plane[c];
        float t  = 2.0f * (px*pl.x + py*pl.y + pz*pl.z + pl.w);
        float rx = fmaf(-t, pl.x, px);
        float ry = fmaf(-t, pl.y, py);
        float rz = fmaf(-t, pl.z, pz);
        int v0 = min(RES_ - 1, max(0, __float2int_rd(rx * (float)RES_)));
        int v1 = min(RES_ - 1, max(0, __float2int_rd(ry * (float)RES_)));
        int v2 = min(RES_ - 1, max(0, __float2int_rd(rz * (float)RES_)));
        float4 cpv = __ldg(&cpb[(v0 << 10) | (v1 << 5) | v2]);
        float dx = rx - cpv.x, dy = ry - cpv.y, dz = rz - cpv.z;
        acc += sqrtf(fmaf(dx, dx, fmaf(dy, dy, dz * dz)));
    }

    // Deterministic block reduction (fixed order), no float atomics.
#pragma unroll
    for (int off = 16; off >= 1; off >>= 1)
        acc += __shfl_xor_sync(0xffffffffu, acc, off);
    __shared__ float ws[8];
    const int wid = threadIdx.x >> 5;
    if ((threadIdx.x & 31) == 0) ws[wid] = acc;
    __syncthreads();
    if (threadIdx.x == 0) {
        float s = 0.0f;
#pragma unroll
        for (int w = 0; w < 8; w++) s += ws[w];
        g_partials[blockIdx.x] = s;
    }

    // ---- last-block final reduction ----
    __shared__ bool is_last;
    __threadfence();
    if (threadIdx.x == 0) {
        int done = atomicAdd(&g_count, 1);
        is_last = (done == NB - 1);
    }
    __syncthreads();
    if (!is_last) return;

    // Regularizer: 25 * mean_b ||n_hat n_hat^T - I||_F  (warp 0, one lane/batch)
    __shared__ float reg_s;
    if (threadIdx.x < 32) {
        const float* yp = y_pred + threadIdx.x * 16;
        float nh[4][3];
#pragma unroll
        for (int c = 0; c < 4; c++) {
            float nx = yp[c*4+0], ny = yp[c*4+1], nz = yp[c*4+2];
            float inv = rsqrtf(nx*nx + ny*ny + nz*nz);
            nh[c][0] = nx*inv; nh[c][1] = ny*inv; nh[c][2] = nz*inv;
        }
        float s = 0.0f;
#pragma unroll
        for (int c = 0; c < 4; c++)
#pragma unroll
            for (int e = 0; e < 4; e++) {
                float g = nh[c][0]*nh[e][0] + nh[c][1]*nh[e][1] + nh[c][2]*nh[e][2]
                          - (c == e ? 1.0f : 0.0f);
                s += g * g;
            }
        float reg = sqrtf(s);
#pragma unroll
        for (int off = 16; off >= 1; off >>= 1)
            reg += __shfl_xor_sync(0xffffffffu, reg, off);
        if (threadIdx.x == 0) reg_s = 25.0f * reg * (1.0f / (float)B_);
    }

    // Sum all 2048 partials in fixed order (float4 loads, 2 per thread).
    __shared__ float red[256];
    const float4* p4 = (const float4*)g_partials;
    float4 u = p4[threadIdx.x];
    float4 v = p4[threadIdx.x + 256];
    red[threadIdx.x] = (u.x + u.y + u.z + u.w) + (v.x + v.y + v.z + v.w);
    __syncthreads();
#pragma unroll
    for (int stride = 128; stride >= 1; stride >>= 1) {
        if (threadIdx.x < stride) red[threadIdx.x] += red[threadIdx.x + stride];
        __syncthreads();
    }
    if (threadIdx.x == 0) {
        out[0]  = red[0] * (1.0f / (float)N_) + reg_s;
        g_count = 0;                               // reset for next graph replay
    }
}

extern "C" void kernel_launch(void* const* d_in, const int* in_sizes, int n_in,
                              void* d_out, int out_size) {
    const float* y_pred = (const float*)d_in[0];
    const float* points = (const float*)d_in[1];
    // d_in[2] = voxel_grid — unused by the reference math.
    const float4* cp4   = (const float4*)d_in[3];
    float* out = (float*)d_out;

    pad_kernel<<<NVOX / 4 / 256, 256>>>(cp4);
    refl_kernel<<<NB, 256>>>(y_pred, points, out);
}